// round 13
// baseline (speedup 1.0000x reference)
#include <cuda_runtime.h>
#include <cstdint>

// Problem constants (from reference)
#define E_NUM 128
#define R_NUM 65536
#define S_NUM 100000
#define ER (E_NUM * R_NUM)          // 8,388,608 floats per table

// Interleaved scratch accumulator: scratch[2*(e*R+r)+0] = delta-a,
//                                  scratch[2*(e*R+r)+1] = delta-b
// 2*ER floats = 64 MiB, static device global (no allocation).
__device__ float g_scratch[2u * ER];

// ---------------------------------------------------------------------------
// Kernel 1: TMA bulk-store fill (measured 11.3us vs 12.4 for STG/memset —
// the pure-write path caps ~5.5 TB/s on every mechanism; this is the best).
// Each CTA zeroes a 32KB SMEM staging buffer, then one cp.async.bulk
// SMEM->GMEM (UTMASTG) for its 32KB slice.
// ---------------------------------------------------------------------------
#define FILL_CHUNK 32768
__global__ void __launch_bounds__(128) tma_fill_kernel(char* __restrict__ dst) {
    __shared__ __align__(128) char buf[FILL_CHUNK];
    float4* b4 = reinterpret_cast<float4*>(buf);
    const float4 z = make_float4(0.f, 0.f, 0.f, 0.f);
    #pragma unroll
    for (int i = threadIdx.x; i < FILL_CHUNK / 16; i += 128) b4[i] = z;
    __syncthreads();
    if (threadIdx.x == 0) {
        asm volatile("fence.proxy.async.shared::cta;" ::: "memory");
        uint32_t saddr = (uint32_t)__cvta_generic_to_shared(buf);
        char* g = dst + (size_t)blockIdx.x * FILL_CHUNK;
        asm volatile(
            "cp.async.bulk.global.shared::cta.bulk_group [%0], [%1], %2;"
            :: "l"(g), "r"(saddr), "n"(FILL_CHUNK) : "memory");
        asm volatile("cp.async.bulk.commit_group;" ::: "memory");
        asm volatile("cp.async.bulk.wait_group 0;" ::: "memory");
    }
}

// ---------------------------------------------------------------------------
// Kernel 2: scatter-add (MONOLITHIC; untouched champion). One thread per 4
// (sample, estimator) pairs; 4x red.global.add.v2.f32. 12.8M RED lanes at
// the per-SM random-sector wavefront floor: 62us exact.
// ---------------------------------------------------------------------------
__global__ void __launch_bounds__(256) scatter_v2x4_kernel(
        const int4* __restrict__ sr4,
        const float* __restrict__ da,
        const float* __restrict__ db) {
    int t = blockIdx.x * blockDim.x + threadIdx.x;   // [0, S*E/4) exact grid
    int e0 = (t & 31) << 2;                          // e = e0..e0+3
    int s  = t >> 5;                                 // warp-uniform
    int4 r = __ldg(sr4 + t);                         // coalesced 16B
    float va = __ldg(da + s);                        // broadcast
    float vb = __ldg(db + s);

    float* base = g_scratch + 2u * (size_t)e0 * R_NUM;
    float* p0 = base + 2u * (size_t)r.x;
    float* p1 = base + 2u * ((size_t)R_NUM + (size_t)r.y);
    float* p2 = base + 2u * (2u * (size_t)R_NUM + (size_t)r.z);
    float* p3 = base + 2u * (3u * (size_t)R_NUM + (size_t)r.w);
    asm volatile("red.global.add.v2.f32 [%0], {%1, %2};" :: "l"(p0), "f"(va), "f"(vb) : "memory");
    asm volatile("red.global.add.v2.f32 [%0], {%1, %2};" :: "l"(p1), "f"(va), "f"(vb) : "memory");
    asm volatile("red.global.add.v2.f32 [%0], {%1, %2};" :: "l"(p2), "f"(va), "f"(vb) : "memory");
    asm volatile("red.global.add.v2.f32 [%0], {%1, %2};" :: "l"(p3), "f"(va), "f"(vb) : "memory");
}

// ---------------------------------------------------------------------------
// Kernel 3: merge, 2 tiles per thread for doubled MLP. Thread i handles
// float4 indices i and i + ER/8 (both coalesced). All 8 loads batched up
// front (MLP_p1 ~8): 4 scratch loads via __ldcg (L2-resident, skip L1),
// 4 cold a/b loads via __ldcs; 4 streaming stores via __stcs.
// ---------------------------------------------------------------------------
__global__ void __launch_bounds__(256) merge_x2_kernel(
        const float4* __restrict__ a,
        const float4* __restrict__ b,
        float4* __restrict__ out) {
    int i = blockIdx.x * blockDim.x + threadIdx.x;   // [0, ER/8) exact grid
    int j = i + ER / 8;                              // second tile
    const float4* s4 = reinterpret_cast<const float4*>(g_scratch);

    // Batch all loads first (independent -> deep MLP).
    float4 q0 = __ldcg(s4 + 2 * i + 0);   // {a0,b0,a1,b1} tile0
    float4 q1 = __ldcg(s4 + 2 * i + 1);   // {a2,b2,a3,b3} tile0
    float4 q2 = __ldcg(s4 + 2 * j + 0);   // tile1
    float4 q3 = __ldcg(s4 + 2 * j + 1);
    float4 va0 = __ldcs(a + i);
    float4 vb0 = __ldcs(b + i);
    float4 va1 = __ldcs(a + j);
    float4 vb1 = __ldcs(b + j);

    __stcs(out + i,
           make_float4(va0.x + q0.x, va0.y + q0.z, va0.z + q1.x, va0.w + q1.z));
    __stcs(out + ER / 4 + i,
           make_float4(vb0.x + q0.y, vb0.y + q0.w, vb0.z + q1.y, vb0.w + q1.w));
    __stcs(out + j,
           make_float4(va1.x + q2.x, va1.y + q2.z, va1.z + q3.x, va1.w + q3.z));
    __stcs(out + ER / 4 + j,
           make_float4(vb1.x + q2.y, vb1.y + q2.w, vb1.z + q3.y, vb1.w + q3.w));
}

extern "C" void kernel_launch(void* const* d_in, const int* in_sizes, int n_in,
                              void* d_out, int out_size) {
    const float* a  = (const float*)d_in[0];          // [E, R]
    const float* b  = (const float*)d_in[1];          // [E, R]
    const int*   sr = (const int*)d_in[2];            // [S, E]
    const float* da = (const float*)d_in[3];          // [S]
    const float* db = (const float*)d_in[4];          // [S]
    float* out = (float*)d_out;                       // [2, E, R]

    // Resolve scratch symbol address once (host-side query, no allocation).
    static char* sp = [] {
        void* p = nullptr;
        cudaGetSymbolAddress(&p, g_scratch);
        return (char*)p;
    }();

    // Phase 1: TMA bulk-store fill (64 MiB / 32KB = 2048 CTAs).
    tma_fill_kernel<<<(int)(sizeof(float) * 2u * ER / FILL_CHUNK), 128>>>(sp);

    // Phase 2: monolithic scatter (12500 blocks exact).
    scatter_v2x4_kernel<<<S_NUM * E_NUM / 4 / 256, 256>>>((const int4*)sr, da, db);

    // Phase 3: merge x2 (ER/8 threads = 4096 blocks exact).
    merge_x2_kernel<<<ER / 8 / 256, 256>>>((const float4*)a, (const float4*)b,
                                           (float4*)out);
}

// round 14
// speedup vs baseline: 1.0208x; 1.0208x over previous
#include <cuda_runtime.h>
#include <cstdint>

// Problem constants (from reference)
#define E_NUM 128
#define R_NUM 65536
#define S_NUM 100000
#define ER (E_NUM * R_NUM)          // 8,388,608 floats per table

// Interleaved scratch accumulator: scratch[2*(e*R+r)+0] = delta-a,
//                                  scratch[2*(e*R+r)+1] = delta-b
// 2*ER floats = 64 MiB, static device global (no allocation).
__device__ float g_scratch[2u * ER];

// ---------------------------------------------------------------------------
// Kernel 1: TMA bulk-store fill (best measured fill: 11.3us). Each CTA zeroes
// a 32KB SMEM staging buffer, then one cp.async.bulk SMEM->GMEM (UTMASTG).
// Leaves scratch zeros resident in L2 for the scatter.
// ---------------------------------------------------------------------------
#define FILL_CHUNK 32768
__global__ void __launch_bounds__(128) tma_fill_kernel(char* __restrict__ dst) {
    __shared__ __align__(128) char buf[FILL_CHUNK];
    float4* b4 = reinterpret_cast<float4*>(buf);
    const float4 z = make_float4(0.f, 0.f, 0.f, 0.f);
    #pragma unroll
    for (int i = threadIdx.x; i < FILL_CHUNK / 16; i += 128) b4[i] = z;
    __syncthreads();
    if (threadIdx.x == 0) {
        asm volatile("fence.proxy.async.shared::cta;" ::: "memory");
        uint32_t saddr = (uint32_t)__cvta_generic_to_shared(buf);
        char* g = dst + (size_t)blockIdx.x * FILL_CHUNK;
        asm volatile(
            "cp.async.bulk.global.shared::cta.bulk_group [%0], [%1], %2;"
            :: "l"(g), "r"(saddr), "n"(FILL_CHUNK) : "memory");
        asm volatile("cp.async.bulk.commit_group;" ::: "memory");
        asm volatile("cp.async.bulk.wait_group 0;" ::: "memory");
    }
}

// ---------------------------------------------------------------------------
// Kernel 2: scatter-add (monolithic). KEY CHANGE: sr/da/db are read-once
// streams -> __ldcs (evict-first) so they do NOT evict the L2-resident
// zeroed scratch. 4x red.global.add.v2.f32 per thread; 12.8M RED lanes at
// the per-SM random-sector wavefront floor: 62us (SM-bound, DRAM idle).
// ---------------------------------------------------------------------------
__global__ void __launch_bounds__(256) scatter_v2x4_kernel(
        const int4* __restrict__ sr4,
        const float* __restrict__ da,
        const float* __restrict__ db) {
    int t = blockIdx.x * blockDim.x + threadIdx.x;   // [0, S*E/4) exact grid
    int e0 = (t & 31) << 2;                          // e = e0..e0+3
    int s  = t >> 5;                                 // warp-uniform
    int4 r = __ldcs(sr4 + t);                        // streaming, evict-first
    float va = __ldcs(da + s);                       // broadcast, streaming
    float vb = __ldcs(db + s);

    float* base = g_scratch + 2u * (size_t)e0 * R_NUM;
    float* p0 = base + 2u * (size_t)r.x;
    float* p1 = base + 2u * ((size_t)R_NUM + (size_t)r.y);
    float* p2 = base + 2u * (2u * (size_t)R_NUM + (size_t)r.z);
    float* p3 = base + 2u * (3u * (size_t)R_NUM + (size_t)r.w);
    asm volatile("red.global.add.v2.f32 [%0], {%1, %2};" :: "l"(p0), "f"(va), "f"(vb) : "memory");
    asm volatile("red.global.add.v2.f32 [%0], {%1, %2};" :: "l"(p1), "f"(va), "f"(vb) : "memory");
    asm volatile("red.global.add.v2.f32 [%0], {%1, %2};" :: "l"(p2), "f"(va), "f"(vb) : "memory");
    asm volatile("red.global.add.v2.f32 [%0], {%1, %2};" :: "l"(p3), "f"(va), "f"(vb) : "memory");
}

// ---------------------------------------------------------------------------
// Kernel 3: merge: out[0] = a + scratch.a (deinterleave), out[1] = b +
// scratch.b. scratch now L2-hot (protected during scatter) -> __ldcg;
// a/b cold one-shot -> __ldcs; out -> __stcs. DRAM bytes ~128-135MB.
// ---------------------------------------------------------------------------
__global__ void __launch_bounds__(256) merge_kernel(
        const float4* __restrict__ a,
        const float4* __restrict__ b,
        float4* __restrict__ out) {
    int i = blockIdx.x * blockDim.x + threadIdx.x;   // [0, ER/4) exact grid
    const float4* s4 = reinterpret_cast<const float4*>(g_scratch);
    float4 p0 = __ldcg(s4 + 2 * i + 0);   // {a0,b0,a1,b1}
    float4 p1 = __ldcg(s4 + 2 * i + 1);   // {a2,b2,a3,b3}
    float4 va = __ldcs(a + i);
    float4 vb = __ldcs(b + i);
    __stcs(out + i,
           make_float4(va.x + p0.x, va.y + p0.z, va.z + p1.x, va.w + p1.z));
    __stcs(out + ER / 4 + i,
           make_float4(vb.x + p0.y, vb.y + p0.w, vb.z + p1.y, vb.w + p1.w));
}

extern "C" void kernel_launch(void* const* d_in, const int* in_sizes, int n_in,
                              void* d_out, int out_size) {
    const float* a  = (const float*)d_in[0];          // [E, R]
    const float* b  = (const float*)d_in[1];          // [E, R]
    const int*   sr = (const int*)d_in[2];            // [S, E]
    const float* da = (const float*)d_in[3];          // [S]
    const float* db = (const float*)d_in[4];          // [S]
    float* out = (float*)d_out;                       // [2, E, R]

    // Resolve scratch symbol address once (host-side query, no allocation).
    static char* sp = [] {
        void* p = nullptr;
        cudaGetSymbolAddress(&p, g_scratch);
        return (char*)p;
    }();

    // Phase 1: TMA bulk-store fill (64 MiB / 32KB = 2048 CTAs).
    tma_fill_kernel<<<(int)(sizeof(float) * 2u * ER / FILL_CHUNK), 128>>>(sp);

    // Phase 2: monolithic scatter (12500 blocks exact).
    scatter_v2x4_kernel<<<S_NUM * E_NUM / 4 / 256, 256>>>((const int4*)sr, da, db);

    // Phase 3: merge + deinterleave into output (8192 blocks exact).
    merge_kernel<<<ER / 4 / 256, 256>>>((const float4*)a, (const float4*)b,
                                        (float4*)out);
}